// round 14
// baseline (speedup 1.0000x reference)
#include <cuda_runtime.h>
#include <cuda_fp16.h>
#include <math.h>
#include <stdint.h>

// ---------------------------------------------------------------------------
// GCN_27797028339919 — round 14
//  * R13 math; shorter dependent chain (8 stages): zero -> fill -> markcompact
//    -> aggx -> gemm_S -> gather2 -> gemm_root -> head
//  * fill: 4 edges/thread (int4) -> 4x MLP on the atomic chains
//  * mark+compact fused (atomicExch dedup append); dinv computed on the fly
//  * aggx: 4-deep neighbor pipeline
// ---------------------------------------------------------------------------

#define MAX_N 100000
#define MAX_R 2048
#define SLOTS 64

__device__ uint32_t g_xh[(size_t)MAX_N * 128];
__device__ uint32_t g_gx_td[(size_t)MAX_N * 128];
__device__ uint32_t g_gx_bu[(size_t)MAX_N * 128];
__device__ uint32_t g_B_td[(size_t)MAX_N * 64];
__device__ uint32_t g_B_bu[(size_t)MAX_N * 64];
__device__ uint32_t g_wh[(size_t)384 * 128];
__device__ int   g_cur_td[MAX_N];
__device__ int   g_cur_bu[MAX_N];
__device__ int   g_srcs_td[(size_t)MAX_N * SLOTS];
__device__ int   g_srcs_bu[(size_t)MAX_N * SLOTS];
__device__ int   g_mark_td[MAX_N];
__device__ int   g_mark_bu[MAX_N];
__device__ int   g_list_td[MAX_N];
__device__ int   g_list_bu[MAX_N];
__device__ int   g_inv_td[MAX_N];
__device__ int   g_inv_bu[MAX_N];
__device__ int   g_listcnt[2];
__device__ uint32_t g_g_td[(size_t)MAX_R * 64];
__device__ uint32_t g_g_bu[(size_t)MAX_R * 64];
__device__ uint32_t g_r_td[(size_t)MAX_R * 64];
__device__ uint32_t g_r_bu[(size_t)MAX_R * 64];

static inline int ceil_div(int a, int b) { return (a + b - 1) / b; }

__device__ __forceinline__ uint32_t h2_u32(__half2 h) {
    return *reinterpret_cast<uint32_t*>(&h);
}
__device__ __forceinline__ __half2 u32_h2(uint32_t u) {
    return *reinterpret_cast<__half2*>(&u);
}
__device__ __forceinline__ float4 h4_to_f4(uint2 v) {
    float2 lo = __half22float2(u32_h2(v.x));
    float2 hi = __half22float2(u32_h2(v.y));
    return make_float4(lo.x, lo.y, hi.x, hi.y);
}
__device__ __forceinline__ float elu1(float x) {
    return x > 0.f ? x : expm1f(x);
}
__device__ __forceinline__ float dinv_of(int cnt) {
    return rsqrtf((float)cnt + 1.0f);
}

// ---------------- prep kernels ----------------

__global__ void convert_x_kernel(const float* __restrict__ x,
                                 uint32_t* __restrict__ xh, int n4) {
    int i = blockIdx.x * blockDim.x + threadIdx.x;
    if (i >= n4) return;
    float4 v = *(const float4*)&x[(size_t)i * 4];
    uint2 o;
    o.x = h2_u32(__floats2half2_rn(v.x, v.y));
    o.y = h2_u32(__floats2half2_rn(v.z, v.w));
    *(uint2*)&xh[(size_t)i * 2] = o;
}

__global__ void pack_w_kernel(const float* __restrict__ w1, const float* __restrict__ w2,
                              const float* __restrict__ w3, const float* __restrict__ w4,
                              uint32_t* __restrict__ wh) {
    int i = blockIdx.x * blockDim.x + threadIdx.x;
    if (i >= 384 * 128) return;
    int prow = i >> 7;
    int n = i & 127;
    const float* w; int p;
    if (prow < 128)      { w = w1; p = prow; }
    else if (prow < 192) { w = w2; p = prow - 128; }
    else if (prow < 320) { w = w3; p = prow - 192; }
    else                 { w = w4; p = prow - 320; }
    float a = w[(size_t)(2 * p) * 128 + n];
    float b = w[(size_t)(2 * p + 1) * 128 + n];
    wh[i] = h2_u32(__floats2half2_rn(a, b));
}

__global__ void zero_kernel(int* ua, int* ub, int* ma, int* mb, int* lc, int n) {
    int i = blockIdx.x * blockDim.x + threadIdx.x;
    if (i < n) { ua[i] = 0; ub[i] = 0; ma[i] = 0; mb[i] = 0; }
    if (i < 2) lc[i] = 0;
}

// 4 edges per thread via int4: 4 independent atomic->store chains.
__global__ void fill_kernel(const int* __restrict__ src0, const int* __restrict__ dst0,
                            const int* __restrict__ src1, const int* __restrict__ dst1,
                            int* cur0, int* cur1,
                            int* __restrict__ srcs0, int* __restrict__ srcs1, int E) {
    int e4 = blockIdx.x * blockDim.x + threadIdx.x;
    int e0 = e4 * 4;
    if (e0 >= E) return;
    const int* src; const int* dst; int* cur; int* srcs;
    if (blockIdx.y) { src = src1; dst = dst1; cur = cur1; srcs = srcs1; }
    else            { src = src0; dst = dst0; cur = cur0; srcs = srcs0; }

    if (e0 + 4 <= E) {
        int4 s = __ldg((const int4*)&src[e0]);
        int4 d = __ldg((const int4*)&dst[e0]);
        int p0 = atomicAdd(&cur[d.x], 1);
        int p1 = atomicAdd(&cur[d.y], 1);
        int p2 = atomicAdd(&cur[d.z], 1);
        int p3 = atomicAdd(&cur[d.w], 1);
        if (p0 < SLOTS) srcs[(size_t)d.x * SLOTS + p0] = s.x;
        if (p1 < SLOTS) srcs[(size_t)d.y * SLOTS + p1] = s.y;
        if (p2 < SLOTS) srcs[(size_t)d.z * SLOTS + p2] = s.z;
        if (p3 < SLOTS) srcs[(size_t)d.w * SLOTS + p3] = s.w;
    } else {
        for (int e = e0; e < E; e++) {
            int d = __ldg(&dst[e]);
            int p = atomicAdd(&cur[d], 1);
            if (p < SLOTS) srcs[(size_t)d * SLOTS + p] = __ldg(&src[e]);
        }
    }
}

// fused mark+compact: dedup-append S = roots ∪ bucket-srcs(roots)
__global__ void markcompact_kernel(const int* __restrict__ roots,
                                   const int* __restrict__ cnt0, const int* __restrict__ srcs0,
                                   const int* __restrict__ cnt1, const int* __restrict__ srcs1,
                                   int* mark0, int* mark1,
                                   int* __restrict__ list0, int* __restrict__ list1,
                                   int* __restrict__ inv0, int* __restrict__ inv1,
                                   int* listcnt, int R) {
    int idx = blockIdx.x * blockDim.x + threadIdx.x;
    if (idx >= R * 65) return;
    int r = idx / 65;
    int s = idx % 65;
    const int* cnt; const int* srcs; int* mark; int* list; int* inv; int b = blockIdx.y;
    if (b) { cnt = cnt1; srcs = srcs1; mark = mark1; list = list1; inv = inv1; }
    else   { cnt = cnt0; srcs = srcs0; mark = mark0; list = list0; inv = inv0; }
    int node = __ldg(&roots[r]);
    if (s < 64) {
        int c = min(__ldg(&cnt[node]), SLOTS);
        if (s >= c) return;
        node = __ldg(&srcs[(size_t)node * SLOTS + s]);
    }
    if (atomicExch(&mark[node], 1) == 0) {
        int p = atomicAdd(&listcnt[b], 1);
        list[p] = node;
        inv[node] = p;
    }
}

// ---------------- x-space aggregation over S (dual, 4-deep pipeline) --------
// gx[idx] = dinv[node]*(sum dinv[s]*xh[s] + dinv[node]*xh[node])

__global__ __launch_bounds__(256)
void aggx_kernel(const uint32_t* __restrict__ xh,
                 uint32_t* __restrict__ gx0, uint32_t* __restrict__ gx1,
                 const int* __restrict__ cnt0, const int* __restrict__ cnt1,
                 const int* __restrict__ srcs0, const int* __restrict__ srcs1,
                 const int* __restrict__ list0, const int* __restrict__ list1,
                 const int* __restrict__ listcnt) {
    uint32_t* gx; const int* cnt; const int* srcs; const int* list; int lc;
    if (blockIdx.y) { gx = gx1; cnt = cnt1; srcs = srcs1; list = list1; lc = __ldg(&listcnt[1]); }
    else            { gx = gx0; cnt = cnt0; srcs = srcs0; list = list0; lc = __ldg(&listcnt[0]); }

    int idx = (blockIdx.x * 256 + threadIdx.x) >> 5;
    if (idx >= lc) return;
    int node = __ldg(&list[idx]);
    int lane = threadIdx.x & 31;

    const uint4* X4 = (const uint4*)xh;
    const int cn = min(__ldg(&cnt[node]), SLOTS);
    const float dd = dinv_of(__ldg(&cnt[node]));

    float acc[8];
    {
        uint4 v = __ldg(&X4[(size_t)node * 32 + lane]);
        float2 f0 = __half22float2(u32_h2(v.x));
        float2 f1 = __half22float2(u32_h2(v.y));
        float2 f2 = __half22float2(u32_h2(v.z));
        float2 f3 = __half22float2(u32_h2(v.w));
        acc[0] = dd * f0.x; acc[1] = dd * f0.y;
        acc[2] = dd * f1.x; acc[3] = dd * f1.y;
        acc[4] = dd * f2.x; acc[5] = dd * f2.y;
        acc[6] = dd * f3.x; acc[7] = dd * f3.y;
    }

    const int* sp = &srcs[(size_t)node * SLOTS];

    int i = 0;
    for (; i + 4 <= cn; i += 4) {
        int4 s4 = *(const int4*)&sp[i];
        int c0 = __ldg(&cnt[s4.x]);
        int c1 = __ldg(&cnt[s4.y]);
        int c2 = __ldg(&cnt[s4.z]);
        int c3 = __ldg(&cnt[s4.w]);
        uint4 v0 = __ldg(&X4[(size_t)s4.x * 32 + lane]);
        uint4 v1 = __ldg(&X4[(size_t)s4.y * 32 + lane]);
        uint4 v2 = __ldg(&X4[(size_t)s4.z * 32 + lane]);
        uint4 v3 = __ldg(&X4[(size_t)s4.w * 32 + lane]);
        float n0 = dinv_of(c0), n1 = dinv_of(c1), n2 = dinv_of(c2), n3 = dinv_of(c3);
        {
            float2 a0 = __half22float2(u32_h2(v0.x)), a1 = __half22float2(u32_h2(v0.y));
            float2 a2 = __half22float2(u32_h2(v0.z)), a3 = __half22float2(u32_h2(v0.w));
            acc[0] = fmaf(n0, a0.x, acc[0]); acc[1] = fmaf(n0, a0.y, acc[1]);
            acc[2] = fmaf(n0, a1.x, acc[2]); acc[3] = fmaf(n0, a1.y, acc[3]);
            acc[4] = fmaf(n0, a2.x, acc[4]); acc[5] = fmaf(n0, a2.y, acc[5]);
            acc[6] = fmaf(n0, a3.x, acc[6]); acc[7] = fmaf(n0, a3.y, acc[7]);
        }
        {
            float2 a0 = __half22float2(u32_h2(v1.x)), a1 = __half22float2(u32_h2(v1.y));
            float2 a2 = __half22float2(u32_h2(v1.z)), a3 = __half22float2(u32_h2(v1.w));
            acc[0] = fmaf(n1, a0.x, acc[0]); acc[1] = fmaf(n1, a0.y, acc[1]);
            acc[2] = fmaf(n1, a1.x, acc[2]); acc[3] = fmaf(n1, a1.y, acc[3]);
            acc[4] = fmaf(n1, a2.x, acc[4]); acc[5] = fmaf(n1, a2.y, acc[5]);
            acc[6] = fmaf(n1, a3.x, acc[6]); acc[7] = fmaf(n1, a3.y, acc[7]);
        }
        {
            float2 a0 = __half22float2(u32_h2(v2.x)), a1 = __half22float2(u32_h2(v2.y));
            float2 a2 = __half22float2(u32_h2(v2.z)), a3 = __half22float2(u32_h2(v2.w));
            acc[0] = fmaf(n2, a0.x, acc[0]); acc[1] = fmaf(n2, a0.y, acc[1]);
            acc[2] = fmaf(n2, a1.x, acc[2]); acc[3] = fmaf(n2, a1.y, acc[3]);
            acc[4] = fmaf(n2, a2.x, acc[4]); acc[5] = fmaf(n2, a2.y, acc[5]);
            acc[6] = fmaf(n2, a3.x, acc[6]); acc[7] = fmaf(n2, a3.y, acc[7]);
        }
        {
            float2 a0 = __half22float2(u32_h2(v3.x)), a1 = __half22float2(u32_h2(v3.y));
            float2 a2 = __half22float2(u32_h2(v3.z)), a3 = __half22float2(u32_h2(v3.w));
            acc[0] = fmaf(n3, a0.x, acc[0]); acc[1] = fmaf(n3, a0.y, acc[1]);
            acc[2] = fmaf(n3, a1.x, acc[2]); acc[3] = fmaf(n3, a1.y, acc[3]);
            acc[4] = fmaf(n3, a2.x, acc[4]); acc[5] = fmaf(n3, a2.y, acc[5]);
            acc[6] = fmaf(n3, a3.x, acc[6]); acc[7] = fmaf(n3, a3.y, acc[7]);
        }
    }
    for (; i < cn; i++) {
        int s = __ldg(&sp[i]);
        float n = dinv_of(__ldg(&cnt[s]));
        uint4 v = __ldg(&X4[(size_t)s * 32 + lane]);
        float2 a0 = __half22float2(u32_h2(v.x)), a1 = __half22float2(u32_h2(v.y));
        float2 a2 = __half22float2(u32_h2(v.z)), a3 = __half22float2(u32_h2(v.w));
        acc[0] = fmaf(n, a0.x, acc[0]); acc[1] = fmaf(n, a0.y, acc[1]);
        acc[2] = fmaf(n, a1.x, acc[2]); acc[3] = fmaf(n, a1.y, acc[3]);
        acc[4] = fmaf(n, a2.x, acc[4]); acc[5] = fmaf(n, a2.y, acc[5]);
        acc[6] = fmaf(n, a3.x, acc[6]); acc[7] = fmaf(n, a3.y, acc[7]);
    }

    uint4 o;
    o.x = h2_u32(__floats2half2_rn(dd * acc[0], dd * acc[1]));
    o.y = h2_u32(__floats2half2_rn(dd * acc[2], dd * acc[3]));
    o.z = h2_u32(__floats2half2_rn(dd * acc[4], dd * acc[5]));
    o.w = h2_u32(__floats2half2_rn(dd * acc[6], dd * acc[7]));
    ((uint4*)gx)[(size_t)idx * 32 + lane] = o;
}

// ---------------- fp16 mma helpers ----------------

__device__ __forceinline__ void mma_f16(float* c, const uint32_t* a, const uint32_t* b) {
    asm volatile(
        "mma.sync.aligned.m16n8k16.row.col.f32.f16.f16.f32 "
        "{%0,%1,%2,%3}, {%4,%5,%6,%7}, {%8,%9}, {%0,%1,%2,%3};"
        : "+f"(c[0]), "+f"(c[1]), "+f"(c[2]), "+f"(c[3])
        : "r"(a[0]), "r"(a[1]), "r"(a[2]), "r"(a[3]),
          "r"(b[0]), "r"(b[1]));
}

__device__ __forceinline__ int sw_idx(int k, int m) {
    return k * 136 + (m ^ (((k >> 2) & 3) << 3));
}

// ---------------- gemm_S dual: B1s[idx] = dinv*elu(gx@W + b) ----------------

__global__ __launch_bounds__(256, 2)
void gemm_S(const uint32_t* __restrict__ X0, const uint32_t* __restrict__ X1,
            const uint32_t* __restrict__ W0, const uint32_t* __restrict__ W1,
            uint32_t* __restrict__ Y0, uint32_t* __restrict__ Y1,
            const int* __restrict__ cnt0, const int* __restrict__ cnt1,
            const float* __restrict__ bias0, const float* __restrict__ bias1,
            const int* __restrict__ list0, const int* __restrict__ list1,
            const int* __restrict__ listcnt) {
    const uint32_t* X; const uint32_t* W; uint32_t* Y;
    const int* cnt; const float* bias; const int* list; int M;
    if (blockIdx.y) { X = X1; W = W1; Y = Y1; cnt = cnt1; bias = bias1; list = list1; M = __ldg(&listcnt[1]); }
    else            { X = X0; W = W0; Y = Y0; cnt = cnt0; bias = bias0; list = list0; M = __ldg(&listcnt[0]); }

    constexpr int K2 = 128;
    constexpr int NC = 8;

    const int row0 = blockIdx.x * 128;
    if (row0 >= M) return;

    __shared__ uint32_t xs[2][16 * 136];
    __shared__ uint32_t ws[2][16 * 136];

    const int tid  = threadIdx.x;
    const int lane = tid & 31;
    const int wid  = tid >> 5;
    const int g    = lane >> 2;
    const int tig  = lane & 3;
    const int mbase = (wid & 1) * 64;
    const int nbase = (wid >> 1) * 32;

    const int xr  = tid >> 2;
    const int xkq = (tid & 3) * 4;
    const int wkr = tid >> 5;
    const int wcq = (tid & 31) * 4;

    float c[4][4][4];
#pragma unroll
    for (int mf = 0; mf < 4; mf++)
#pragma unroll
        for (int nf = 0; nf < 4; nf++)
#pragma unroll
            for (int q = 0; q < 4; q++) c[mf][nf][q] = 0.f;

    uint4 xv[2], wv[2];

    auto loadg = [&](int t) {
        const int p0 = t * 16;
#pragma unroll
        for (int l = 0; l < 2; l++) {
            int r = xr + l * 64;
            int grow = row0 + r;
            xv[l] = (grow < M) ? *(const uint4*)&X[(size_t)grow * K2 + p0 + xkq]
                               : make_uint4(0u, 0u, 0u, 0u);
            wv[l] = *(const uint4*)&W[(size_t)(p0 + wkr + l * 8) * 128 + wcq];
        }
    };
    auto store_s = [&](int buf) {
#pragma unroll
        for (int l = 0; l < 2; l++) {
            int r = xr + l * 64;
            xs[buf][sw_idx(xkq + 0, r)] = xv[l].x;
            xs[buf][sw_idx(xkq + 1, r)] = xv[l].y;
            xs[buf][sw_idx(xkq + 2, r)] = xv[l].z;
            xs[buf][sw_idx(xkq + 3, r)] = xv[l].w;
            *(uint4*)&ws[buf][sw_idx(wkr + l * 8, wcq)] = wv[l];
        }
    };
    auto compute = [&](int buf) {
#pragma unroll
        for (int ks = 0; ks < 2; ks++) {
            const int klo = ks * 8 + tig;
            const int khi = klo + 4;
            uint32_t a[4][4], b[4][2];
#pragma unroll
            for (int mf = 0; mf < 4; mf++) {
                int m0 = mbase + mf * 16 + g;
                a[mf][0] = xs[buf][sw_idx(klo, m0)];
                a[mf][1] = xs[buf][sw_idx(klo, m0 + 8)];
                a[mf][2] = xs[buf][sw_idx(khi, m0)];
                a[mf][3] = xs[buf][sw_idx(khi, m0 + 8)];
            }
#pragma unroll
            for (int nf = 0; nf < 4; nf++) {
                int n0 = nbase + nf * 8 + g;
                b[nf][0] = ws[buf][sw_idx(klo, n0)];
                b[nf][1] = ws[buf][sw_idx(khi, n0)];
            }
#pragma unroll
            for (int mf = 0; mf < 4; mf++)
#pragma unroll
                for (int nf = 0; nf < 4; nf++)
                    mma_f16(c[mf][nf], a[mf], b[nf]);
        }
    };

    loadg(0);
    store_s(0);
    __syncthreads();

    for (int t = 0; t < NC; t++) {
        if (t + 1 < NC) loadg(t + 1);
        compute(t & 1);
        if (t + 1 < NC) {
            store_s((t + 1) & 1);
            __syncthreads();
        }
    }

#pragma unroll
    for (int mf = 0; mf < 4; mf++) {
        int r0 = row0 + mbase + mf * 16 + g;
        float dlo = 0.f, dhi = 0.f;
        if (r0 < M)     dlo = dinv_of(__ldg(&cnt[__ldg(&list[r0])]));
        if (r0 + 8 < M) dhi = dinv_of(__ldg(&cnt[__ldg(&list[r0 + 8])]));
#pragma unroll
        for (int nf = 0; nf < 4; nf++) {
            int ncol = nbase + nf * 8 + tig * 2;
            int np = ncol >> 1;
            float b0 = __ldg(&bias[ncol]);
            float b1 = __ldg(&bias[ncol + 1]);
            if (r0 < M)
                Y[(size_t)r0 * 64 + np] =
                    h2_u32(__floats2half2_rn(dlo * elu1(b0 + c[mf][nf][0]),
                                             dlo * elu1(b1 + c[mf][nf][1])));
            if (r0 + 8 < M)
                Y[(size_t)(r0 + 8) * 64 + np] =
                    h2_u32(__floats2half2_rn(dhi * elu1(b0 + c[mf][nf][2]),
                                             dhi * elu1(b1 + c[mf][nf][3])));
        }
    }
}

// ---------------- root layer-2 GEMM dual: elu(bias + g@W) ----------------

__global__ __launch_bounds__(256, 2)
void gemm_root(const uint32_t* __restrict__ X0, const uint32_t* __restrict__ X1,
               const uint32_t* __restrict__ W0, const uint32_t* __restrict__ W1,
               uint32_t* __restrict__ Y0, uint32_t* __restrict__ Y1,
               const float* __restrict__ bias0, const float* __restrict__ bias1,
               int M) {
    const uint32_t* X; const uint32_t* W; uint32_t* Y; const float* bias;
    if (blockIdx.y) { X = X1; W = W1; Y = Y1; bias = bias1; }
    else            { X = X0; W = W0; Y = Y0; bias = bias0; }

    constexpr int K2 = 64;
    constexpr int NC = 4;

    __shared__ uint32_t xs[2][16 * 136];
    __shared__ uint32_t ws[2][16 * 136];

    const int tid  = threadIdx.x;
    const int lane = tid & 31;
    const int wid  = tid >> 5;
    const int g    = lane >> 2;
    const int tig  = lane & 3;
    const int mbase = (wid & 1) * 64;
    const int nbase = (wid >> 1) * 32;
    const int row0  = blockIdx.x * 128;

    const int xr  = tid >> 2;
    const int xkq = (tid & 3) * 4;
    const int wkr = tid >> 5;
    const int wcq = (tid & 31) * 4;

    float c[4][4][4];
#pragma unroll
    for (int mf = 0; mf < 4; mf++)
#pragma unroll
        for (int nf = 0; nf < 4; nf++)
#pragma unroll
            for (int q = 0; q < 4; q++) c[mf][nf][q] = 0.f;

    uint4 xv[2], wv[2];

    auto loadg = [&](int t) {
        const int p0 = t * 16;
#pragma unroll
        for (int l = 0; l < 2; l++) {
            int r = xr + l * 64;
            int grow = row0 + r;
            xv[l] = (grow < M) ? *(const uint4*)&X[(size_t)grow * K2 + p0 + xkq]
                               : make_uint4(0u, 0u, 0u, 0u);
            wv[l] = *(const uint4*)&W[(size_t)(p0 + wkr + l * 8) * 128 + wcq];
        }
    };
    auto store_s = [&](int buf) {
#pragma unroll
        for (int l = 0; l < 2; l++) {
            int r = xr + l * 64;
            xs[buf][sw_idx(xkq + 0, r)] = xv[l].x;
            xs[buf][sw_idx(xkq + 1, r)] = xv[l].y;
            xs[buf][sw_idx(xkq + 2, r)] = xv[l].z;
            xs[buf][sw_idx(xkq + 3, r)] = xv[l].w;
            *(uint4*)&ws[buf][sw_idx(wkr + l * 8, wcq)] = wv[l];
        }
    };
    auto compute = [&](int buf) {
#pragma unroll
        for (int ks = 0; ks < 2; ks++) {
            const int klo = ks * 8 + tig;
            const int khi = klo + 4;
            uint32_t a[4][4], b[4][2];
#pragma unroll
            for (int mf = 0; mf < 4; mf++) {
                int m0 = mbase + mf * 16 + g;
                a[mf][0] = xs[buf][sw_idx(klo, m0)];
                a[mf][1] = xs[buf][sw_idx(klo, m0 + 8)];
                a[mf][2] = xs[buf][sw_idx(khi, m0)];
                a[mf][3] = xs[buf][sw_idx(khi, m0 + 8)];
            }
#pragma unroll
            for (int nf = 0; nf < 4; nf++) {
                int n0 = nbase + nf * 8 + g;
                b[nf][0] = ws[buf][sw_idx(klo, n0)];
                b[nf][1] = ws[buf][sw_idx(khi, n0)];
            }
#pragma unroll
            for (int mf = 0; mf < 4; mf++)
#pragma unroll
                for (int nf = 0; nf < 4; nf++)
                    mma_f16(c[mf][nf], a[mf], b[nf]);
        }
    };

    loadg(0);
    store_s(0);
    __syncthreads();

    for (int t = 0; t < NC; t++) {
        if (t + 1 < NC) loadg(t + 1);
        compute(t & 1);
        if (t + 1 < NC) {
            store_s((t + 1) & 1);
            __syncthreads();
        }
    }

#pragma unroll
    for (int mf = 0; mf < 4; mf++) {
        int r0 = row0 + mbase + mf * 16 + g;
#pragma unroll
        for (int nf = 0; nf < 4; nf++) {
            int ncol = nbase + nf * 8 + tig * 2;
            int np = ncol >> 1;
            float b0 = __ldg(&bias[ncol]);
            float b1 = __ldg(&bias[ncol + 1]);
            if (r0 < M)
                Y[(size_t)r0 * 64 + np] =
                    h2_u32(__floats2half2_rn(elu1(b0 + c[mf][nf][0]),
                                             elu1(b1 + c[mf][nf][1])));
            if (r0 + 8 < M)
                Y[(size_t)(r0 + 8) * 64 + np] =
                    h2_u32(__floats2half2_rn(elu1(b0 + c[mf][nf][2]),
                                             elu1(b1 + c[mf][nf][3])));
        }
    }
}

// ---------------- layer-2 gather at roots (dual, compact via inv) -----------

__global__ __launch_bounds__(256)
void gather2_kernel(const uint32_t* __restrict__ B0, const uint32_t* __restrict__ B1,
                    const int* __restrict__ roots,
                    const int* __restrict__ cnt0, const int* __restrict__ cnt1,
                    const int* __restrict__ srcs0, const int* __restrict__ srcs1,
                    const int* __restrict__ inv0, const int* __restrict__ inv1,
                    uint32_t* __restrict__ gbuf0, uint32_t* __restrict__ gbuf1, int R) {
    const uint32_t* B; const int* cnt; const int* srcs; const int* inv; uint32_t* gbuf;
    if (blockIdx.y) { B = B1; cnt = cnt1; srcs = srcs1; inv = inv1; gbuf = gbuf1; }
    else            { B = B0; cnt = cnt0; srcs = srcs0; inv = inv0; gbuf = gbuf0; }

    int r = blockIdx.x * 8 + (threadIdx.x >> 5);
    if (r >= R) return;
    int lane = threadIdx.x & 31;
    int node = __ldg(&roots[r]);

    const uint2* B2 = (const uint2*)B;
    float4 acc = h4_to_f4(__ldg(&B2[(size_t)__ldg(&inv[node]) * 32 + lane]));

    int c = min(__ldg(&cnt[node]), SLOTS);
    const int* sp = &srcs[(size_t)node * SLOTS];
    for (int i = 0; i < c; i++) {
        int s = __ldg(&sp[i]);
        float4 v = h4_to_f4(__ldg(&B2[(size_t)__ldg(&inv[s]) * 32 + lane]));
        acc.x += v.x; acc.y += v.y; acc.z += v.z; acc.w += v.w;
    }

    float dd = dinv_of(__ldg(&cnt[node]));
    uint2 o;
    o.x = h2_u32(__floats2half2_rn(dd * acc.x, dd * acc.y));
    o.y = h2_u32(__floats2half2_rn(dd * acc.z, dd * acc.w));
    ((uint2*)gbuf)[(size_t)r * 32 + lane] = o;
}

// ---------------- fused head ----------------

__global__ __launch_bounds__(256)
void head_kernel(const uint32_t* __restrict__ Rtd, const uint32_t* __restrict__ Rbu,
                 const float* __restrict__ fcw, const float* __restrict__ fcb,
                 float* __restrict__ out, int R) {
    int r = blockIdx.x * 8 + (threadIdx.x >> 5);
    if (r >= R) return;
    int lane = threadIdx.x & 31;

    float4 ftd = h4_to_f4(((const uint2*)Rtd)[(size_t)r * 32 + lane]);
    float4 fbu = h4_to_f4(((const uint2*)Rbu)[(size_t)r * 32 + lane]);

    float s0 = 0.f, s1 = 0.f, s2 = 0.f, s3 = 0.f;
    const float* ft = &ftd.x;
    const float* fb = &fbu.x;
#pragma unroll
    for (int j = 0; j < 4; j++) {
        int k = lane * 4 + j;
        float4 wt = *(const float4*)&fcw[(size_t)k * 4];
        float4 wb = *(const float4*)&fcw[(size_t)(128 + k) * 4];
        s0 = fmaf(ft[j], wt.x, fmaf(fb[j], wb.x, s0));
        s1 = fmaf(ft[j], wt.y, fmaf(fb[j], wb.y, s1));
        s2 = fmaf(ft[j], wt.z, fmaf(fb[j], wb.z, s2));
        s3 = fmaf(ft[j], wt.w, fmaf(fb[j], wb.w, s3));
    }
#pragma unroll
    for (int off = 16; off; off >>= 1) {
        s0 += __shfl_xor_sync(0xffffffffu, s0, off);
        s1 += __shfl_xor_sync(0xffffffffu, s1, off);
        s2 += __shfl_xor_sync(0xffffffffu, s2, off);
        s3 += __shfl_xor_sync(0xffffffffu, s3, off);
    }
    if (lane == 0) {
        s0 += fcb[0]; s1 += fcb[1]; s2 += fcb[2]; s3 += fcb[3];
        float m = fmaxf(fmaxf(s0, s1), fmaxf(s2, s3));
        float s = expf(s0 - m) + expf(s1 - m) + expf(s2 - m) + expf(s3 - m);
        float lse = m + logf(s);
        float4 o = make_float4(s0 - lse, s1 - lse, s2 - lse, s3 - lse);
        *(float4*)&out[(size_t)r * 4] = o;
    }
}

// ---------------------------------------------------------------------------

extern "C" void kernel_launch(void* const* d_in, const int* in_sizes, int n_in,
                              void* d_out, int out_size) {
    const float* x       = (const float*)d_in[0];
    const int*   ei_td   = (const int*)d_in[1];
    const int*   ei_bu   = (const int*)d_in[2];
    const int*   rootidx = (const int*)d_in[3];
    const float* w1 = (const float*)d_in[4];
    const float* b1 = (const float*)d_in[5];
    const float* w2 = (const float*)d_in[6];
    const float* b2 = (const float*)d_in[7];
    const float* w3 = (const float*)d_in[8];
    const float* b3 = (const float*)d_in[9];
    const float* w4 = (const float*)d_in[10];
    const float* b4 = (const float*)d_in[11];
    const float* fcw = (const float*)d_in[12];
    const float* fcb = (const float*)d_in[13];
    float* out = (float*)d_out;

    const int N = in_sizes[0] / 256;
    const int E = in_sizes[1] / 2;
    const int R = in_sizes[3];

    const int* src_td = ei_td;
    const int* dst_td = ei_td + E;
    const int* src_bu = ei_bu;
    const int* dst_bu = ei_bu + E;

    uint32_t *xh, *gx_td, *gx_bu, *B_td, *B_bu, *wh, *g_td, *g_bu, *r_td, *r_bu;
    int *cur_td, *cur_bu, *srcs_td, *srcs_bu;
    int *list_td, *list_bu, *inv_td, *inv_bu, *listcnt;
    int *mark_td, *mark_bu;
    cudaGetSymbolAddress((void**)&xh, g_xh);
    cudaGetSymbolAddress((void**)&gx_td, g_gx_td);
    cudaGetSymbolAddress((void**)&gx_bu, g_gx_bu);
    cudaGetSymbolAddress((void**)&B_td, g_B_td);
    cudaGetSymbolAddress((void**)&B_bu, g_B_bu);
    cudaGetSymbolAddress((void**)&wh, g_wh);
    cudaGetSymbolAddress((void**)&cur_td, g_cur_td);
    cudaGetSymbolAddress((void**)&cur_bu, g_cur_bu);
    cudaGetSymbolAddress((void**)&srcs_td, g_srcs_td);
    cudaGetSymbolAddress((void**)&srcs_bu, g_srcs_bu);
    cudaGetSymbolAddress((void**)&mark_td, g_mark_td);
    cudaGetSymbolAddress((void**)&mark_bu, g_mark_bu);
    cudaGetSymbolAddress((void**)&list_td, g_list_td);
    cudaGetSymbolAddress((void**)&list_bu, g_list_bu);
    cudaGetSymbolAddress((void**)&inv_td, g_inv_td);
    cudaGetSymbolAddress((void**)&inv_bu, g_inv_bu);
    cudaGetSymbolAddress((void**)&listcnt, g_listcnt);
    cudaGetSymbolAddress((void**)&g_td, g_g_td);
    cudaGetSymbolAddress((void**)&g_bu, g_g_bu);
    cudaGetSymbolAddress((void**)&r_td, g_r_td);
    cudaGetSymbolAddress((void**)&r_bu, g_r_bu);

    const uint32_t* w1h = wh;
    const uint32_t* w2h = wh + 128 * 128;
    const uint32_t* w3h = wh + 192 * 128;
    const uint32_t* w4h = wh + 320 * 128;

    static cudaStream_t sB = nullptr;
    static cudaEvent_t evFork, evPrep;
    if (!sB) {
        cudaStreamCreateWithFlags(&sB, cudaStreamNonBlocking);
        cudaEventCreateWithFlags(&evFork, cudaEventDisableTiming);
        cudaEventCreateWithFlags(&evPrep, cudaEventDisableTiming);
    }
    cudaStream_t sA = 0;

    const dim3 agg_grid(ceil_div(N, 8), 2);
    const dim3 gemmS_grid(ceil_div(N, 128), 2);
    const dim3 gather_grid(ceil_div(R, 8), 2);
    const dim3 root_grid(ceil_div(R, 128), 2);

    cudaEventRecord(evFork, sA);
    cudaStreamWaitEvent(sB, evFork, 0);

    // sB: prep chain
    zero_kernel<<<ceil_div(N, 256), 256, 0, sB>>>(cur_td, cur_bu,
                                                  mark_td, mark_bu, listcnt, N);
    fill_kernel<<<dim3(ceil_div(E, 1024), 2), 256, 0, sB>>>(
        src_td, dst_td, src_bu, dst_bu, cur_td, cur_bu, srcs_td, srcs_bu, E);
    markcompact_kernel<<<dim3(ceil_div(R * 65, 256), 2), 256, 0, sB>>>(
        rootidx, cur_td, srcs_td, cur_bu, srcs_bu, mark_td, mark_bu,
        list_td, list_bu, inv_td, inv_bu, listcnt, R);
    cudaEventRecord(evPrep, sB);

    // sA: convert + pack (independent), then the compute tail
    convert_x_kernel<<<ceil_div(N * 64, 256), 256, 0, sA>>>(x, xh, N * 64);
    pack_w_kernel<<<192, 256, 0, sA>>>(w1, w2, w3, w4, wh);
    cudaStreamWaitEvent(sA, evPrep, 0);
    aggx_kernel<<<agg_grid, 256, 0, sA>>>(xh, gx_td, gx_bu, cur_td, cur_bu,
                                          srcs_td, srcs_bu, list_td, list_bu, listcnt);
    gemm_S<<<gemmS_grid, 256, 0, sA>>>(gx_td, gx_bu, w1h, w3h, B_td, B_bu,
                                       cur_td, cur_bu, b1, b3,
                                       list_td, list_bu, listcnt);
    gather2_kernel<<<gather_grid, 256, 0, sA>>>(B_td, B_bu, rootidx,
                                                cur_td, cur_bu, srcs_td, srcs_bu,
                                                inv_td, inv_bu, g_td, g_bu, R);
    gemm_root<<<root_grid, 256, 0, sA>>>(g_td, g_bu, w2h, w4h, r_td, r_bu,
                                         b2, b4, R);
    head_kernel<<<ceil_div(R, 8), 256, 0, sA>>>(r_td, r_bu, fcw, fcb, out, R);
}

// round 15
// speedup vs baseline: 1.0241x; 1.0241x over previous
#include <cuda_runtime.h>
#include <cuda_fp16.h>
#include <math.h>
#include <stdint.h>

// ---------------------------------------------------------------------------
// GCN_27797028339919 — round 15
//  * R11 structure (best measured: full fp32-read GEMMs start at t=0 on two
//    streams; list-restricted agg; root-only layer 2; fused head)
//  * prep shortened: zero -> fill(int4 x4 edges) -> markcompact(atomicExch);
//    dinv computed on the fly from cnt everywhere (dinv arrays deleted)
// ---------------------------------------------------------------------------

#define MAX_N 100000
#define MAX_R 2048
#define SLOTS 64

__device__ uint32_t g_A_td[(size_t)MAX_N * 64];
__device__ uint32_t g_B_td[(size_t)MAX_N * 64];
__device__ uint32_t g_A_bu[(size_t)MAX_N * 64];
__device__ uint32_t g_B_bu[(size_t)MAX_N * 64];
__device__ uint32_t g_wh[(size_t)128 * 128];        // packed W2|W4 (root gemm)
__device__ int   g_cur_td[MAX_N];
__device__ int   g_cur_bu[MAX_N];
__device__ int   g_srcs_td[(size_t)MAX_N * SLOTS];
__device__ int   g_srcs_bu[(size_t)MAX_N * SLOTS];
__device__ int   g_mark_td[MAX_N];
__device__ int   g_mark_bu[MAX_N];
__device__ int   g_list_td[MAX_N];
__device__ int   g_list_bu[MAX_N];
__device__ int   g_listcnt[2];
__device__ uint32_t g_g_td[(size_t)MAX_R * 64];
__device__ uint32_t g_g_bu[(size_t)MAX_R * 64];
__device__ uint32_t g_r_td[(size_t)MAX_R * 64];
__device__ uint32_t g_r_bu[(size_t)MAX_R * 64];

static inline int ceil_div(int a, int b) { return (a + b - 1) / b; }

__device__ __forceinline__ uint32_t h2_u32(__half2 h) {
    return *reinterpret_cast<uint32_t*>(&h);
}
__device__ __forceinline__ __half2 u32_h2(uint32_t u) {
    return *reinterpret_cast<__half2*>(&u);
}
__device__ __forceinline__ float4 h4_to_f4(uint2 v) {
    float2 lo = __half22float2(u32_h2(v.x));
    float2 hi = __half22float2(u32_h2(v.y));
    return make_float4(lo.x, lo.y, hi.x, hi.y);
}
__device__ __forceinline__ float elu1(float x) {
    return x > 0.f ? x : expm1f(x);
}
__device__ __forceinline__ float dinv_of(int cnt) {
    return rsqrtf((float)cnt + 1.0f);
}

// ---------------- prep kernels ----------------

__global__ void pack_w_kernel(const float* __restrict__ w2, const float* __restrict__ w4,
                              uint32_t* __restrict__ wh) {
    int i = blockIdx.x * blockDim.x + threadIdx.x;
    if (i >= 128 * 128) return;
    int prow = i >> 7;
    int n = i & 127;
    const float* w; int p;
    if (prow < 64) { w = w2; p = prow; }
    else           { w = w4; p = prow - 64; }
    float a = w[(size_t)(2 * p) * 128 + n];
    float b = w[(size_t)(2 * p + 1) * 128 + n];
    wh[i] = h2_u32(__floats2half2_rn(a, b));
}

__global__ void zero_kernel(int* ua, int* ub, int* ma, int* mb, int* lc, int n) {
    int i = blockIdx.x * blockDim.x + threadIdx.x;
    if (i < n) { ua[i] = 0; ub[i] = 0; ma[i] = 0; mb[i] = 0; }
    if (i < 2) lc[i] = 0;
}

// 4 edges per thread via int4: 4 independent atomic->store chains.
__global__ void fill_kernel(const int* __restrict__ src0, const int* __restrict__ dst0,
                            const int* __restrict__ src1, const int* __restrict__ dst1,
                            int* cur0, int* cur1,
                            int* __restrict__ srcs0, int* __restrict__ srcs1, int E) {
    int e0 = (blockIdx.x * blockDim.x + threadIdx.x) * 4;
    if (e0 >= E) return;
    const int* src; const int* dst; int* cur; int* srcs;
    if (blockIdx.y) { src = src1; dst = dst1; cur = cur1; srcs = srcs1; }
    else            { src = src0; dst = dst0; cur = cur0; srcs = srcs0; }

    if (e0 + 4 <= E) {
        int4 s = __ldg((const int4*)&src[e0]);
        int4 d = __ldg((const int4*)&dst[e0]);
        int p0 = atomicAdd(&cur[d.x], 1);
        int p1 = atomicAdd(&cur[d.y], 1);
        int p2 = atomicAdd(&cur[d.z], 1);
        int p3 = atomicAdd(&cur[d.w], 1);
        if (p0 < SLOTS) srcs[(size_t)d.x * SLOTS + p0] = s.x;
        if (p1 < SLOTS) srcs[(size_t)d.y * SLOTS + p1] = s.y;
        if (p2 < SLOTS) srcs[(size_t)d.z * SLOTS + p2] = s.z;
        if (p3 < SLOTS) srcs[(size_t)d.w * SLOTS + p3] = s.w;
    } else {
        for (int e = e0; e < E; e++) {
            int d = __ldg(&dst[e]);
            int p = atomicAdd(&cur[d], 1);
            if (p < SLOTS) srcs[(size_t)d * SLOTS + p] = __ldg(&src[e]);
        }
    }
}

// fused mark+compact: dedup-append S = roots ∪ bucket-srcs(roots)
__global__ void markcompact_kernel(const int* __restrict__ roots,
                                   const int* __restrict__ cnt0, const int* __restrict__ srcs0,
                                   const int* __restrict__ cnt1, const int* __restrict__ srcs1,
                                   int* mark0, int* mark1,
                                   int* __restrict__ list0, int* __restrict__ list1,
                                   int* listcnt, int R) {
    int idx = blockIdx.x * blockDim.x + threadIdx.x;
    if (idx >= R * 65) return;
    int r = idx / 65;
    int s = idx % 65;
    const int* cnt; const int* srcs; int* mark; int* list; int b = blockIdx.y;
    if (b) { cnt = cnt1; srcs = srcs1; mark = mark1; list = list1; }
    else   { cnt = cnt0; srcs = srcs0; mark = mark0; list = list0; }
    int node = __ldg(&roots[r]);
    if (s < 64) {
        int c = min(__ldg(&cnt[node]), SLOTS);
        if (s >= c) return;
        node = __ldg(&srcs[(size_t)node * SLOTS + s]);
    }
    if (atomicExch(&mark[node], 1) == 0) {
        int p = atomicAdd(&listcnt[b], 1);
        list[p] = node;
    }
}

// ---------------- fp16 mma helpers ----------------

__device__ __forceinline__ void mma_f16(float* c, const uint32_t* a, const uint32_t* b) {
    asm volatile(
        "mma.sync.aligned.m16n8k16.row.col.f32.f16.f16.f32 "
        "{%0,%1,%2,%3}, {%4,%5,%6,%7}, {%8,%9}, {%0,%1,%2,%3};"
        : "+f"(c[0]), "+f"(c[1]), "+f"(c[2]), "+f"(c[3])
        : "r"(a[0]), "r"(a[1]), "r"(a[2]), "r"(a[3]),
          "r"(b[0]), "r"(b[1]));
}

__device__ __forceinline__ int sw_idx(int k, int m) {
    return k * 136 + (m ^ (((k >> 2) & 3) << 3));
}

// ---------------- layer-1 GEMM: A_raw[M,64u32] = fp16(x[M,256]f32 @ Wf32) ---
// zero external dependencies: fp32 x and fp32 W converted during staging.

__global__ __launch_bounds__(256, 2)
void gemm_l1(const float* __restrict__ X, const float* __restrict__ W,
             uint32_t* __restrict__ Y, int M) {
    constexpr int K = 256;
    constexpr int NC = K / 32;

    __shared__ uint32_t xs[2][16 * 136];
    __shared__ uint32_t ws[2][16 * 136];

    const int tid  = threadIdx.x;
    const int lane = tid & 31;
    const int wid  = tid >> 5;
    const int g    = lane >> 2;
    const int tig  = lane & 3;
    const int mbase = (wid & 1) * 64;
    const int nbase = (wid >> 1) * 32;
    const int row0  = blockIdx.x * 128;

    const int xr  = tid >> 2;
    const int xkq = (tid & 3) * 4;
    const int wkr = tid >> 5;
    const int wcq = (tid & 31) * 4;

    float c[4][4][4];
#pragma unroll
    for (int mf = 0; mf < 4; mf++)
#pragma unroll
        for (int nf = 0; nf < 4; nf++)
#pragma unroll
            for (int q = 0; q < 4; q++) c[mf][nf][q] = 0.f;

    float4 xa[2], xb[2];
    uint4 wq[2];

    auto loadg = [&](int t) {
        const int k0 = t * 32 + xkq * 2;
#pragma unroll
        for (int l = 0; l < 2; l++) {
            int r = xr + l * 64;
            int grow = row0 + r;
            if (grow < M) {
                xa[l] = *(const float4*)&X[(size_t)grow * K + k0];
                xb[l] = *(const float4*)&X[(size_t)grow * K + k0 + 4];
            } else {
                xa[l] = make_float4(0.f, 0.f, 0.f, 0.f);
                xb[l] = make_float4(0.f, 0.f, 0.f, 0.f);
            }
            int kr = (t * 16 + wkr + l * 8) * 2;
            float4 wa = *(const float4*)&W[(size_t)kr * 128 + wcq];
            float4 wb = *(const float4*)&W[(size_t)(kr + 1) * 128 + wcq];
            wq[l] = make_uint4(h2_u32(__floats2half2_rn(wa.x, wb.x)),
                               h2_u32(__floats2half2_rn(wa.y, wb.y)),
                               h2_u32(__floats2half2_rn(wa.z, wb.z)),
                               h2_u32(__floats2half2_rn(wa.w, wb.w)));
        }
    };
    auto store_s = [&](int buf) {
#pragma unroll
        for (int l = 0; l < 2; l++) {
            int r = xr + l * 64;
            xs[buf][sw_idx(xkq + 0, r)] = h2_u32(__floats2half2_rn(xa[l].x, xa[l].y));
            xs[buf][sw_idx(xkq + 1, r)] = h2_u32(__floats2half2_rn(xa[l].z, xa[l].w));
            xs[buf][sw_idx(xkq + 2, r)] = h2_u32(__floats2half2_rn(xb[l].x, xb[l].y));
            xs[buf][sw_idx(xkq + 3, r)] = h2_u32(__floats2half2_rn(xb[l].z, xb[l].w));
            *(uint4*)&ws[buf][sw_idx(wkr + l * 8, wcq)] = wq[l];
        }
    };
    auto compute = [&](int buf) {
#pragma unroll
        for (int ks = 0; ks < 2; ks++) {
            const int klo = ks * 8 + tig;
            const int khi = klo + 4;
            uint32_t a[4][4], b[4][2];
#pragma unroll
            for (int mf = 0; mf < 4; mf++) {
                int m0 = mbase + mf * 16 + g;
                a[mf][0] = xs[buf][sw_idx(klo, m0)];
                a[mf][1] = xs[buf][sw_idx(klo, m0 + 8)];
                a[mf][2] = xs[buf][sw_idx(khi, m0)];
                a[mf][3] = xs[buf][sw_idx(khi, m0 + 8)];
            }
#pragma unroll
            for (int nf = 0; nf < 4; nf++) {
                int n0 = nbase + nf * 8 + g;
                b[nf][0] = ws[buf][sw_idx(klo, n0)];
                b[nf][1] = ws[buf][sw_idx(khi, n0)];
            }
#pragma unroll
            for (int mf = 0; mf < 4; mf++)
#pragma unroll
                for (int nf = 0; nf < 4; nf++)
                    mma_f16(c[mf][nf], a[mf], b[nf]);
        }
    };

    loadg(0);
    store_s(0);
    __syncthreads();

    for (int t = 0; t < NC; t++) {
        if (t + 1 < NC) loadg(t + 1);
        compute(t & 1);
        if (t + 1 < NC) {
            store_s((t + 1) & 1);
            __syncthreads();
        }
    }

#pragma unroll
    for (int mf = 0; mf < 4; mf++) {
        int r0 = row0 + mbase + mf * 16 + g;
#pragma unroll
        for (int nf = 0; nf < 4; nf++) {
            int np = (nbase + nf * 8 + tig * 2) >> 1;
            if (r0 < M)
                Y[(size_t)r0 * 64 + np] =
                    h2_u32(__floats2half2_rn(c[mf][nf][0], c[mf][nf][1]));
            if (r0 + 8 < M)
                Y[(size_t)(r0 + 8) * 64 + np] =
                    h2_u32(__floats2half2_rn(c[mf][nf][2], c[mf][nf][3]));
        }
    }
}

// ---------------- root layer-2 GEMM ----------------

__global__ __launch_bounds__(256, 2)
void gemm_root(const uint32_t* __restrict__ X, const uint32_t* __restrict__ W,
               uint32_t* __restrict__ Y, const float* __restrict__ bias, int M) {
    constexpr int K2 = 64;
    constexpr int NC = 4;

    __shared__ uint32_t xs[2][16 * 136];
    __shared__ uint32_t ws[2][16 * 136];

    const int tid  = threadIdx.x;
    const int lane = tid & 31;
    const int wid  = tid >> 5;
    const int g    = lane >> 2;
    const int tig  = lane & 3;
    const int mbase = (wid & 1) * 64;
    const int nbase = (wid >> 1) * 32;
    const int row0  = blockIdx.x * 128;

    const int xr  = tid >> 2;
    const int xkq = (tid & 3) * 4;
    const int wkr = tid >> 5;
    const int wcq = (tid & 31) * 4;

    float c[4][4][4];
#pragma unroll
    for (int mf = 0; mf < 4; mf++)
#pragma unroll
        for (int nf = 0; nf < 4; nf++)
#pragma unroll
            for (int q = 0; q < 4; q++) c[mf][nf][q] = 0.f;

    uint4 xv[2], wv[2];

    auto loadg = [&](int t) {
        const int p0 = t * 16;
#pragma unroll
        for (int l = 0; l < 2; l++) {
            int r = xr + l * 64;
            int grow = row0 + r;
            xv[l] = (grow < M) ? *(const uint4*)&X[(size_t)grow * K2 + p0 + xkq]
                               : make_uint4(0u, 0u, 0u, 0u);
            wv[l] = *(const uint4*)&W[(size_t)(p0 + wkr + l * 8) * 128 + wcq];
        }
    };
    auto store_s = [&](int buf) {
#pragma unroll
        for (int l = 0; l < 2; l++) {
            int r = xr + l * 64;
            xs[buf][sw_idx(xkq + 0, r)] = xv[l].x;
            xs[buf][sw_idx(xkq + 1, r)] = xv[l].y;
            xs[buf][sw_idx(xkq + 2, r)] = xv[l].z;
            xs[buf][sw_idx(xkq + 3, r)] = xv[l].w;
            *(uint4*)&ws[buf][sw_idx(wkr + l * 8, wcq)] = wv[l];
        }
    };
    auto compute = [&](int buf) {
#pragma unroll
        for (int ks = 0; ks < 2; ks++) {
            const int klo = ks * 8 + tig;
            const int khi = klo + 4;
            uint32_t a[4][4], b[4][2];
#pragma unroll
            for (int mf = 0; mf < 4; mf++) {
                int m0 = mbase + mf * 16 + g;
                a[mf][0] = xs[buf][sw_idx(klo, m0)];
                a[mf][1] = xs[buf][sw_idx(klo, m0 + 8)];
                a[mf][2] = xs[buf][sw_idx(khi, m0)];
                a[mf][3] = xs[buf][sw_idx(khi, m0 + 8)];
            }
#pragma unroll
            for (int nf = 0; nf < 4; nf++) {
                int n0 = nbase + nf * 8 + g;
                b[nf][0] = ws[buf][sw_idx(klo, n0)];
                b[nf][1] = ws[buf][sw_idx(khi, n0)];
            }
#pragma unroll
            for (int mf = 0; mf < 4; mf++)
#pragma unroll
                for (int nf = 0; nf < 4; nf++)
                    mma_f16(c[mf][nf], a[mf], b[nf]);
        }
    };

    loadg(0);
    store_s(0);
    __syncthreads();

    for (int t = 0; t < NC; t++) {
        if (t + 1 < NC) loadg(t + 1);
        compute(t & 1);
        if (t + 1 < NC) {
            store_s((t + 1) & 1);
            __syncthreads();
        }
    }

#pragma unroll
    for (int mf = 0; mf < 4; mf++) {
        int r0 = row0 + mbase + mf * 16 + g;
#pragma unroll
        for (int nf = 0; nf < 4; nf++) {
            int ncol = nbase + nf * 8 + tig * 2;
            int np = ncol >> 1;
            float b0 = __ldg(&bias[ncol]);
            float b1 = __ldg(&bias[ncol + 1]);
            if (r0 < M)
                Y[(size_t)r0 * 64 + np] =
                    h2_u32(__floats2half2_rn(elu1(b0 + c[mf][nf][0]),
                                             elu1(b1 + c[mf][nf][1])));
            if (r0 + 8 < M)
                Y[(size_t)(r0 + 8) * 64 + np] =
                    h2_u32(__floats2half2_rn(elu1(b0 + c[mf][nf][2]),
                                             elu1(b1 + c[mf][nf][3])));
        }
    }
}

// ---------------- layer-1 aggregation restricted to S ----------------
// B1s[node] = dinv[n]*elu(bias + dinv[n]*(dinv[n]*A[n] + sum dinv[s]*A[s]))

__global__ __launch_bounds__(256)
void agg_list(const uint32_t* __restrict__ A, uint32_t* __restrict__ B,
              const int* __restrict__ cnt, const int* __restrict__ srcs,
              const float* __restrict__ bias,
              const int* __restrict__ list, const int* __restrict__ listcnt) {
    int idx = (blockIdx.x * 256 + threadIdx.x) >> 5;
    if (idx >= *listcnt) return;
    int node = __ldg(&list[idx]);
    int lane = threadIdx.x & 31;

    const uint2* A2 = (const uint2*)A;
    const float dd = dinv_of(__ldg(&cnt[node]));

    float4 a0 = h4_to_f4(A2[(size_t)node * 32 + lane]);
    float4 acc = make_float4(dd * a0.x, dd * a0.y, dd * a0.z, dd * a0.w);

    int c = min(__ldg(&cnt[node]), SLOTS);
    const int* sp = &srcs[(size_t)node * SLOTS];

    int i = 0;
    for (; i + 4 <= c; i += 4) {
        int4 s4 = *(const int4*)&sp[i];
        float n0 = dinv_of(__ldg(&cnt[s4.x]));
        float n1 = dinv_of(__ldg(&cnt[s4.y]));
        float n2 = dinv_of(__ldg(&cnt[s4.z]));
        float n3 = dinv_of(__ldg(&cnt[s4.w]));
        float4 v0 = h4_to_f4(__ldg(&A2[(size_t)s4.x * 32 + lane]));
        float4 v1 = h4_to_f4(__ldg(&A2[(size_t)s4.y * 32 + lane]));
        float4 v2 = h4_to_f4(__ldg(&A2[(size_t)s4.z * 32 + lane]));
        float4 v3 = h4_to_f4(__ldg(&A2[(size_t)s4.w * 32 + lane]));
        acc.x = fmaf(n0, v0.x, acc.x); acc.y = fmaf(n0, v0.y, acc.y);
        acc.z = fmaf(n0, v0.z, acc.z); acc.w = fmaf(n0, v0.w, acc.w);
        acc.x = fmaf(n1, v1.x, acc.x); acc.y = fmaf(n1, v1.y, acc.y);
        acc.z = fmaf(n1, v1.z, acc.z); acc.w = fmaf(n1, v1.w, acc.w);
        acc.x = fmaf(n2, v2.x, acc.x); acc.y = fmaf(n2, v2.y, acc.y);
        acc.z = fmaf(n2, v2.z, acc.z); acc.w = fmaf(n2, v2.w, acc.w);
        acc.x = fmaf(n3, v3.x, acc.x); acc.y = fmaf(n3, v3.y, acc.y);
        acc.z = fmaf(n3, v3.z, acc.z); acc.w = fmaf(n3, v3.w, acc.w);
    }
    for (; i < c; i++) {
        int s = __ldg(&sp[i]);
        float n = dinv_of(__ldg(&cnt[s]));
        float4 v = h4_to_f4(__ldg(&A2[(size_t)s * 32 + lane]));
        acc.x = fmaf(n, v.x, acc.x); acc.y = fmaf(n, v.y, acc.y);
        acc.z = fmaf(n, v.z, acc.z); acc.w = fmaf(n, v.w, acc.w);
    }

    float4 bv = *(const float4*)&bias[lane * 4];
    acc.x = dd * elu1(fmaf(dd, acc.x, bv.x));
    acc.y = dd * elu1(fmaf(dd, acc.y, bv.y));
    acc.z = dd * elu1(fmaf(dd, acc.z, bv.z));
    acc.w = dd * elu1(fmaf(dd, acc.w, bv.w));

    uint2 o;
    o.x = h2_u32(__floats2half2_rn(acc.x, acc.y));
    o.y = h2_u32(__floats2half2_rn(acc.z, acc.w));
    ((uint2*)B)[(size_t)node * 32 + lane] = o;
}

// ---------------- layer-2 gather at roots ----------------

__global__ __launch_bounds__(256)
void gather2_kernel(const uint32_t* __restrict__ B,
                    const int* __restrict__ roots,
                    const int* __restrict__ cnt, const int* __restrict__ srcs,
                    uint32_t* __restrict__ gbuf, int R) {
    int r = blockIdx.x * 8 + (threadIdx.x >> 5);
    if (r >= R) return;
    int lane = threadIdx.x & 31;
    int node = __ldg(&roots[r]);

    const uint2* B2 = (const uint2*)B;
    float4 acc = h4_to_f4(B2[(size_t)node * 32 + lane]);

    int c = min(__ldg(&cnt[node]), SLOTS);
    const int* sp = &srcs[(size_t)node * SLOTS];
    for (int i = 0; i < c; i++) {
        int s = __ldg(&sp[i]);
        float4 v = h4_to_f4(__ldg(&B2[(size_t)s * 32 + lane]));
        acc.x += v.x; acc.y += v.y; acc.z += v.z; acc.w += v.w;
    }

    float dd = dinv_of(__ldg(&cnt[node]));
    uint2 o;
    o.x = h2_u32(__floats2half2_rn(dd * acc.x, dd * acc.y));
    o.y = h2_u32(__floats2half2_rn(dd * acc.z, dd * acc.w));
    ((uint2*)gbuf)[(size_t)r * 32 + lane] = o;
}

// ---------------- fused head ----------------

__global__ __launch_bounds__(256)
void head_kernel(const uint32_t* __restrict__ Rtd, const uint32_t* __restrict__ Rbu,
                 const float* __restrict__ fcw, const float* __restrict__ fcb,
                 float* __restrict__ out, int R) {
    int r = blockIdx.x * 8 + (threadIdx.x >> 5);
    if (r >= R) return;
    int lane = threadIdx.x & 31;

    float4 ftd = h4_to_f4(((const uint2*)Rtd)[(size_t)r * 32 + lane]);
    float4 fbu = h4_to_f4(((const uint2*)Rbu)[(size_t)r * 32 + lane]);

    float s0 = 0.f, s1 = 0.f, s2 = 0.f, s3 = 0.f;
    const float* ft = &ftd.x;
    const float* fb = &fbu.x;
#pragma unroll
    for (int j = 0; j < 4; j++) {
        int k = lane * 4 + j;
        float4 wt = *(const float4*)&fcw[(size_t)k * 4];
        float4 wb = *(const float4*)&fcw[(size_t)(128 + k) * 4];
        s0 = fmaf(ft[j], wt.x, fmaf(fb[j], wb.x, s0));
        s1 = fmaf(ft[j], wt.y, fmaf(fb[j], wb.y, s1));
        s2 = fmaf(ft[j], wt.z, fmaf(fb[j], wb.z, s2));
        s3 = fmaf(ft[j], wt.w, fmaf(fb[j], wb.w, s3));
    }
#pragma unroll
    for (int off = 16; off; off >>= 1) {
        s0 += __shfl_xor_sync(0xffffffffu, s0, off);
        s1 += __shfl_xor_sync(0xffffffffu, s1, off);
        s2 += __shfl_xor_sync(0xffffffffu, s2, off);
        s3 += __shfl_xor_sync(0xffffffffu, s3, off);
    }
    if (lane == 0) {
        s0 += fcb[0]; s1 += fcb[1]; s2 += fcb[2]; s3 += fcb[3];
        float m = fmaxf(fmaxf(s0, s1), fmaxf(s2, s3));
        float s = expf(s0 - m) + expf(s1 - m) + expf(s2 - m) + expf(s3 - m);
        float lse = m + logf(s);
        float4 o = make_float4(s0 - lse, s1 - lse, s2 - lse, s3 - lse);
        *(float4*)&out[(size_t)r * 4] = o;
    }
}

// ---------------------------------------------------------------------------

extern "C" void kernel_launch(void* const* d_in, const int* in_sizes, int n_in,
                              void* d_out, int out_size) {
    const float* x       = (const float*)d_in[0];
    const int*   ei_td   = (const int*)d_in[1];
    const int*   ei_bu   = (const int*)d_in[2];
    const int*   rootidx = (const int*)d_in[3];
    const float* w1 = (const float*)d_in[4];
    const float* b1 = (const float*)d_in[5];
    const float* w2 = (const float*)d_in[6];
    const float* b2 = (const float*)d_in[7];
    const float* w3 = (const float*)d_in[8];
    const float* b3 = (const float*)d_in[9];
    const float* w4 = (const float*)d_in[10];
    const float* b4 = (const float*)d_in[11];
    const float* fcw = (const float*)d_in[12];
    const float* fcb = (const float*)d_in[13];
    float* out = (float*)d_out;

    const int N = in_sizes[0] / 256;
    const int E = in_sizes[1] / 2;
    const int R = in_sizes[3];

    const int* src_td = ei_td;
    const int* dst_td = ei_td + E;
    const int* src_bu = ei_bu;
    const int* dst_bu = ei_bu + E;

    uint32_t *A_td, *B_td, *A_bu, *B_bu, *wh, *g_td, *g_bu, *r_td, *r_bu;
    int *cur_td, *cur_bu, *srcs_td, *srcs_bu;
    int *list_td, *list_bu, *listcnt, *mark_td, *mark_bu;
    cudaGetSymbolAddress((void**)&A_td, g_A_td);
    cudaGetSymbolAddress((void**)&B_td, g_B_td);
    cudaGetSymbolAddress((void**)&A_bu, g_A_bu);
    cudaGetSymbolAddress((void**)&B_bu, g_B_bu);
    cudaGetSymbolAddress((void**)&wh, g_wh);
    cudaGetSymbolAddress((void**)&cur_td, g_cur_td);
    cudaGetSymbolAddress((void**)&cur_bu, g_cur_bu);
    cudaGetSymbolAddress((void**)&srcs_td, g_srcs_td);
    cudaGetSymbolAddress((void**)&srcs_bu, g_srcs_bu);
    cudaGetSymbolAddress((void**)&mark_td, g_mark_td);
    cudaGetSymbolAddress((void**)&mark_bu, g_mark_bu);
    cudaGetSymbolAddress((void**)&list_td, g_list_td);
    cudaGetSymbolAddress((void**)&list_bu, g_list_bu);
    cudaGetSymbolAddress((void**)&listcnt, g_listcnt);
    cudaGetSymbolAddress((void**)&g_td, g_g_td);
    cudaGetSymbolAddress((void**)&g_bu, g_g_bu);
    cudaGetSymbolAddress((void**)&r_td, g_r_td);
    cudaGetSymbolAddress((void**)&r_bu, g_r_bu);

    const uint32_t* w2h = wh;
    const uint32_t* w4h = wh + 64 * 128;

    static cudaStream_t sB = nullptr, sC = nullptr;
    static cudaEvent_t evFork, evPrep, evBuDone;
    if (!sB) {
        cudaStreamCreateWithFlags(&sB, cudaStreamNonBlocking);
        cudaStreamCreateWithFlags(&sC, cudaStreamNonBlocking);
        cudaEventCreateWithFlags(&evFork,  cudaEventDisableTiming);
        cudaEventCreateWithFlags(&evPrep,  cudaEventDisableTiming);
        cudaEventCreateWithFlags(&evBuDone,cudaEventDisableTiming);
    }
    cudaStream_t sA = 0;

    const int gemm_blocks = ceil_div(N, 128);
    const int agg_blocks  = ceil_div(N, 8);
    const int root_gemm_blocks = ceil_div(R, 128);

    cudaEventRecord(evFork, sA);
    cudaStreamWaitEvent(sB, evFork, 0);
    cudaStreamWaitEvent(sC, evFork, 0);

    // sC: 3-stage prep chain + weight pack (hidden under GEMMs)
    zero_kernel<<<ceil_div(N, 256), 256, 0, sC>>>(cur_td, cur_bu,
                                                  mark_td, mark_bu, listcnt, N);
    fill_kernel<<<dim3(ceil_div(E, 1024), 2), 256, 0, sC>>>(
        src_td, dst_td, src_bu, dst_bu, cur_td, cur_bu, srcs_td, srcs_bu, E);
    markcompact_kernel<<<dim3(ceil_div(R * 65, 256), 2), 256, 0, sC>>>(
        rootidx, cur_td, srcs_td, cur_bu, srcs_bu, mark_td, mark_bu,
        list_td, list_bu, listcnt, R);
    pack_w_kernel<<<64, 256, 0, sC>>>(w2, w4, wh);
    cudaEventRecord(evPrep, sC);

    // td branch on sA (GEMM starts immediately)
    gemm_l1<<<gemm_blocks, 256, 0, sA>>>(x, w1, A_td, N);
    cudaStreamWaitEvent(sA, evPrep, 0);
    agg_list<<<agg_blocks, 256, 0, sA>>>(A_td, B_td, cur_td, srcs_td, b1,
                                         list_td, &listcnt[0]);
    gather2_kernel<<<ceil_div(R, 8), 256, 0, sA>>>(B_td, rootidx, cur_td, srcs_td,
                                                   g_td, R);
    gemm_root<<<root_gemm_blocks, 256, 0, sA>>>(g_td, w2h, r_td, b2, R);

    // bu branch on sB (GEMM starts immediately)
    gemm_l1<<<gemm_blocks, 256, 0, sB>>>(x, w3, A_bu, N);
    cudaStreamWaitEvent(sB, evPrep, 0);
    agg_list<<<agg_blocks, 256, 0, sB>>>(A_bu, B_bu, cur_bu, srcs_bu, b3,
                                         list_bu, &listcnt[1]);
    gather2_kernel<<<ceil_div(R, 8), 256, 0, sB>>>(B_bu, rootidx, cur_bu, srcs_bu,
                                                   g_bu, R);
    gemm_root<<<root_gemm_blocks, 256, 0, sB>>>(g_bu, w4h, r_bu, b4, R);
    cudaEventRecord(evBuDone, sB);

    cudaStreamWaitEvent(sA, evBuDone, 0);
    head_kernel<<<ceil_div(R, 8), 256, 0, sA>>>(r_td, r_bu, fcw, fcb, out, R);
}

// round 16
// speedup vs baseline: 1.0414x; 1.0168x over previous
#include <cuda_runtime.h>
#include <cuda_fp16.h>
#include <math.h>
#include <stdint.h>

// ---------------------------------------------------------------------------
// GCN_27797028339919 — round 16
//  * fused dual-branch layer-1 GEMM: X staged/converted ONCE per tile,
//    multiplied against both W1 and W3 (two accumulator sets) -> X DRAM
//    traffic and staging work halved
//  * prep: zero -> fill(int4) -> markcompact on stream C (hidden)
//  * tails (agg/gather2/root-gemm) dual-grid on the main stream
// ---------------------------------------------------------------------------

#define MAX_N 100000
#define MAX_R 2048
#define SLOTS 64

__device__ uint32_t g_A_td[(size_t)MAX_N * 64];
__device__ uint32_t g_B_td[(size_t)MAX_N * 64];
__device__ uint32_t g_A_bu[(size_t)MAX_N * 64];
__device__ uint32_t g_B_bu[(size_t)MAX_N * 64];
__device__ uint32_t g_wh[(size_t)128 * 128];        // packed W2|W4 (root gemm)
__device__ int   g_cur_td[MAX_N];
__device__ int   g_cur_bu[MAX_N];
__device__ int   g_srcs_td[(size_t)MAX_N * SLOTS];
__device__ int   g_srcs_bu[(size_t)MAX_N * SLOTS];
__device__ int   g_mark_td[MAX_N];
__device__ int   g_mark_bu[MAX_N];
__device__ int   g_list_td[MAX_N];
__device__ int   g_list_bu[MAX_N];
__device__ int   g_listcnt[2];
__device__ uint32_t g_g_td[(size_t)MAX_R * 64];
__device__ uint32_t g_g_bu[(size_t)MAX_R * 64];
__device__ uint32_t g_r_td[(size_t)MAX_R * 64];
__device__ uint32_t g_r_bu[(size_t)MAX_R * 64];

static inline int ceil_div(int a, int b) { return (a + b - 1) / b; }

__device__ __forceinline__ uint32_t h2_u32(__half2 h) {
    return *reinterpret_cast<uint32_t*>(&h);
}
__device__ __forceinline__ __half2 u32_h2(uint32_t u) {
    return *reinterpret_cast<__half2*>(&u);
}
__device__ __forceinline__ float4 h4_to_f4(uint2 v) {
    float2 lo = __half22float2(u32_h2(v.x));
    float2 hi = __half22float2(u32_h2(v.y));
    return make_float4(lo.x, lo.y, hi.x, hi.y);
}
__device__ __forceinline__ float elu1(float x) {
    return x > 0.f ? x : expm1f(x);
}
__device__ __forceinline__ float dinv_of(int cnt) {
    return rsqrtf((float)cnt + 1.0f);
}

// ---------------- prep kernels ----------------

__global__ void pack_w_kernel(const float* __restrict__ w2, const float* __restrict__ w4,
                              uint32_t* __restrict__ wh) {
    int i = blockIdx.x * blockDim.x + threadIdx.x;
    if (i >= 128 * 128) return;
    int prow = i >> 7;
    int n = i & 127;
    const float* w; int p;
    if (prow < 64) { w = w2; p = prow; }
    else           { w = w4; p = prow - 64; }
    float a = w[(size_t)(2 * p) * 128 + n];
    float b = w[(size_t)(2 * p + 1) * 128 + n];
    wh[i] = h2_u32(__floats2half2_rn(a, b));
}

__global__ void zero_kernel(int* ua, int* ub, int* ma, int* mb, int* lc, int n) {
    int i = blockIdx.x * blockDim.x + threadIdx.x;
    if (i < n) { ua[i] = 0; ub[i] = 0; ma[i] = 0; mb[i] = 0; }
    if (i < 2) lc[i] = 0;
}

__global__ void fill_kernel(const int* __restrict__ src0, const int* __restrict__ dst0,
                            const int* __restrict__ src1, const int* __restrict__ dst1,
                            int* cur0, int* cur1,
                            int* __restrict__ srcs0, int* __restrict__ srcs1, int E) {
    int e0 = (blockIdx.x * blockDim.x + threadIdx.x) * 4;
    if (e0 >= E) return;
    const int* src; const int* dst; int* cur; int* srcs;
    if (blockIdx.y) { src = src1; dst = dst1; cur = cur1; srcs = srcs1; }
    else            { src = src0; dst = dst0; cur = cur0; srcs = srcs0; }

    if (e0 + 4 <= E) {
        int4 s = __ldg((const int4*)&src[e0]);
        int4 d = __ldg((const int4*)&dst[e0]);
        int p0 = atomicAdd(&cur[d.x], 1);
        int p1 = atomicAdd(&cur[d.y], 1);
        int p2 = atomicAdd(&cur[d.z], 1);
        int p3 = atomicAdd(&cur[d.w], 1);
        if (p0 < SLOTS) srcs[(size_t)d.x * SLOTS + p0] = s.x;
        if (p1 < SLOTS) srcs[(size_t)d.y * SLOTS + p1] = s.y;
        if (p2 < SLOTS) srcs[(size_t)d.z * SLOTS + p2] = s.z;
        if (p3 < SLOTS) srcs[(size_t)d.w * SLOTS + p3] = s.w;
    } else {
        for (int e = e0; e < E; e++) {
            int d = __ldg(&dst[e]);
            int p = atomicAdd(&cur[d], 1);
            if (p < SLOTS) srcs[(size_t)d * SLOTS + p] = __ldg(&src[e]);
        }
    }
}

__global__ void markcompact_kernel(const int* __restrict__ roots,
                                   const int* __restrict__ cnt0, const int* __restrict__ srcs0,
                                   const int* __restrict__ cnt1, const int* __restrict__ srcs1,
                                   int* mark0, int* mark1,
                                   int* __restrict__ list0, int* __restrict__ list1,
                                   int* listcnt, int R) {
    int idx = blockIdx.x * blockDim.x + threadIdx.x;
    if (idx >= R * 65) return;
    int r = idx / 65;
    int s = idx % 65;
    const int* cnt; const int* srcs; int* mark; int* list; int b = blockIdx.y;
    if (b) { cnt = cnt1; srcs = srcs1; mark = mark1; list = list1; }
    else   { cnt = cnt0; srcs = srcs0; mark = mark0; list = list0; }
    int node = __ldg(&roots[r]);
    if (s < 64) {
        int c = min(__ldg(&cnt[node]), SLOTS);
        if (s >= c) return;
        node = __ldg(&srcs[(size_t)node * SLOTS + s]);
    }
    if (atomicExch(&mark[node], 1) == 0) {
        int p = atomicAdd(&listcnt[b], 1);
        list[p] = node;
    }
}

// ---------------- fp16 mma helpers ----------------

__device__ __forceinline__ void mma_f16(float* c, const uint32_t* a, const uint32_t* b) {
    asm volatile(
        "mma.sync.aligned.m16n8k16.row.col.f32.f16.f16.f32 "
        "{%0,%1,%2,%3}, {%4,%5,%6,%7}, {%8,%9}, {%0,%1,%2,%3};"
        : "+f"(c[0]), "+f"(c[1]), "+f"(c[2]), "+f"(c[3])
        : "r"(a[0]), "r"(a[1]), "r"(a[2]), "r"(a[3]),
          "r"(b[0]), "r"(b[1]));
}

__device__ __forceinline__ int sw_idx(int k, int m) {
    return k * 136 + (m ^ (((k >> 2) & 3) << 3));
}

// ---------------- fused dual layer-1 GEMM ----------------
// Yt = fp16(X@W1), Yb = fp16(X@W3); X fp32 staged+converted once per tile.

__global__ __launch_bounds__(256, 1)
void gemm_l1_dual(const float* __restrict__ X,
                  const float* __restrict__ W1f, const float* __restrict__ W3f,
                  uint32_t* __restrict__ Yt, uint32_t* __restrict__ Yb, int M) {
    constexpr int K = 256;
    constexpr int NC = K / 32;

    __shared__ uint32_t xs[2][16 * 136];
    __shared__ uint32_t w1s[2][16 * 136];
    __shared__ uint32_t w3s[2][16 * 136];

    const int tid  = threadIdx.x;
    const int lane = tid & 31;
    const int wid  = tid >> 5;
    const int g    = lane >> 2;
    const int tig  = lane & 3;
    const int mbase = (wid & 1) * 64;
    const int nbase = (wid >> 1) * 32;
    const int row0  = blockIdx.x * 128;

    const int xr  = tid >> 2;
    const int xkq = (tid & 3) * 4;
    const int wkr = tid >> 5;
    const int wcq = (tid & 31) * 4;

    float c1[4][4][4], c3[4][4][4];
#pragma unroll
    for (int mf = 0; mf < 4; mf++)
#pragma unroll
        for (int nf = 0; nf < 4; nf++)
#pragma unroll
            for (int q = 0; q < 4; q++) { c1[mf][nf][q] = 0.f; c3[mf][nf][q] = 0.f; }

    float4 xa[2], xb[2];
    uint4 wq1[2], wq3[2];

    auto loadg = [&](int t) {
        const int k0 = t * 32 + xkq * 2;
#pragma unroll
        for (int l = 0; l < 2; l++) {
            int r = xr + l * 64;
            int grow = row0 + r;
            if (grow < M) {
                xa[l] = *(const float4*)&X[(size_t)grow * K + k0];
                xb[l] = *(const float4*)&X[(size_t)grow * K + k0 + 4];
            } else {
                xa[l] = make_float4(0.f, 0.f, 0.f, 0.f);
                xb[l] = make_float4(0.f, 0.f, 0.f, 0.f);
            }
            int kr = (t * 16 + wkr + l * 8) * 2;
            {
                float4 wa = *(const float4*)&W1f[(size_t)kr * 128 + wcq];
                float4 wb = *(const float4*)&W1f[(size_t)(kr + 1) * 128 + wcq];
                wq1[l] = make_uint4(h2_u32(__floats2half2_rn(wa.x, wb.x)),
                                    h2_u32(__floats2half2_rn(wa.y, wb.y)),
                                    h2_u32(__floats2half2_rn(wa.z, wb.z)),
                                    h2_u32(__floats2half2_rn(wa.w, wb.w)));
            }
            {
                float4 wa = *(const float4*)&W3f[(size_t)kr * 128 + wcq];
                float4 wb = *(const float4*)&W3f[(size_t)(kr + 1) * 128 + wcq];
                wq3[l] = make_uint4(h2_u32(__floats2half2_rn(wa.x, wb.x)),
                                    h2_u32(__floats2half2_rn(wa.y, wb.y)),
                                    h2_u32(__floats2half2_rn(wa.z, wb.z)),
                                    h2_u32(__floats2half2_rn(wa.w, wb.w)));
            }
        }
    };
    auto store_s = [&](int buf) {
#pragma unroll
        for (int l = 0; l < 2; l++) {
            int r = xr + l * 64;
            xs[buf][sw_idx(xkq + 0, r)] = h2_u32(__floats2half2_rn(xa[l].x, xa[l].y));
            xs[buf][sw_idx(xkq + 1, r)] = h2_u32(__floats2half2_rn(xa[l].z, xa[l].w));
            xs[buf][sw_idx(xkq + 2, r)] = h2_u32(__floats2half2_rn(xb[l].x, xb[l].y));
            xs[buf][sw_idx(xkq + 3, r)] = h2_u32(__floats2half2_rn(xb[l].z, xb[l].w));
            *(uint4*)&w1s[buf][sw_idx(wkr + l * 8, wcq)] = wq1[l];
            *(uint4*)&w3s[buf][sw_idx(wkr + l * 8, wcq)] = wq3[l];
        }
    };
    auto compute = [&](int buf) {
#pragma unroll
        for (int ks = 0; ks < 2; ks++) {
            const int klo = ks * 8 + tig;
            const int khi = klo + 4;
            uint32_t a[4][4], b1[4][2], b3[4][2];
#pragma unroll
            for (int mf = 0; mf < 4; mf++) {
                int m0 = mbase + mf * 16 + g;
                a[mf][0] = xs[buf][sw_idx(klo, m0)];
                a[mf][1] = xs[buf][sw_idx(klo, m0 + 8)];
                a[mf][2] = xs[buf][sw_idx(khi, m0)];
                a[mf][3] = xs[buf][sw_idx(khi, m0 + 8)];
            }
#pragma unroll
            for (int nf = 0; nf < 4; nf++) {
                int n0 = nbase + nf * 8 + g;
                b1[nf][0] = w1s[buf][sw_idx(klo, n0)];
                b1[nf][1] = w1s[buf][sw_idx(khi, n0)];
                b3[nf][0] = w3s[buf][sw_idx(klo, n0)];
                b3[nf][1] = w3s[buf][sw_idx(khi, n0)];
            }
#pragma unroll
            for (int mf = 0; mf < 4; mf++)
#pragma unroll
                for (int nf = 0; nf < 4; nf++) {
                    mma_f16(c1[mf][nf], a[mf], b1[nf]);
                    mma_f16(c3[mf][nf], a[mf], b3[nf]);
                }
        }
    };

    loadg(0);
    store_s(0);
    __syncthreads();

    for (int t = 0; t < NC; t++) {
        if (t + 1 < NC) loadg(t + 1);
        compute(t & 1);
        if (t + 1 < NC) {
            store_s((t + 1) & 1);
            __syncthreads();
        }
    }

#pragma unroll
    for (int mf = 0; mf < 4; mf++) {
        int r0 = row0 + mbase + mf * 16 + g;
#pragma unroll
        for (int nf = 0; nf < 4; nf++) {
            int np = (nbase + nf * 8 + tig * 2) >> 1;
            if (r0 < M) {
                Yt[(size_t)r0 * 64 + np] =
                    h2_u32(__floats2half2_rn(c1[mf][nf][0], c1[mf][nf][1]));
                Yb[(size_t)r0 * 64 + np] =
                    h2_u32(__floats2half2_rn(c3[mf][nf][0], c3[mf][nf][1]));
            }
            if (r0 + 8 < M) {
                Yt[(size_t)(r0 + 8) * 64 + np] =
                    h2_u32(__floats2half2_rn(c1[mf][nf][2], c1[mf][nf][3]));
                Yb[(size_t)(r0 + 8) * 64 + np] =
                    h2_u32(__floats2half2_rn(c3[mf][nf][2], c3[mf][nf][3]));
            }
        }
    }
}

// ---------------- root layer-2 GEMM (dual via grid.y) ----------------

__global__ __launch_bounds__(256, 2)
void gemm_root(const uint32_t* __restrict__ X0, const uint32_t* __restrict__ X1,
               const uint32_t* __restrict__ W0, const uint32_t* __restrict__ W1,
               uint32_t* __restrict__ Y0, uint32_t* __restrict__ Y1,
               const float* __restrict__ bias0, const float* __restrict__ bias1,
               int M) {
    const uint32_t* X; const uint32_t* W; uint32_t* Y; const float* bias;
    if (blockIdx.y) { X = X1; W = W1; Y = Y1; bias = bias1; }
    else            { X = X0; W = W0; Y = Y0; bias = bias0; }

    constexpr int K2 = 64;
    constexpr int NC = 4;

    __shared__ uint32_t xs[2][16 * 136];
    __shared__ uint32_t ws[2][16 * 136];

    const int tid  = threadIdx.x;
    const int lane = tid & 31;
    const int wid  = tid >> 5;
    const int g    = lane >> 2;
    const int tig  = lane & 3;
    const int mbase = (wid & 1) * 64;
    const int nbase = (wid >> 1) * 32;
    const int row0  = blockIdx.x * 128;

    const int xr  = tid >> 2;
    const int xkq = (tid & 3) * 4;
    const int wkr = tid >> 5;
    const int wcq = (tid & 31) * 4;

    float c[4][4][4];
#pragma unroll
    for (int mf = 0; mf < 4; mf++)
#pragma unroll
        for (int nf = 0; nf < 4; nf++)
#pragma unroll
            for (int q = 0; q < 4; q++) c[mf][nf][q] = 0.f;

    uint4 xv[2], wv[2];

    auto loadg = [&](int t) {
        const int p0 = t * 16;
#pragma unroll
        for (int l = 0; l < 2; l++) {
            int r = xr + l * 64;
            int grow = row0 + r;
            xv[l] = (grow < M) ? *(const uint4*)&X[(size_t)grow * K2 + p0 + xkq]
                               : make_uint4(0u, 0u, 0u, 0u);
            wv[l] = *(const uint4*)&W[(size_t)(p0 + wkr + l * 8) * 128 + wcq];
        }
    };
    auto store_s = [&](int buf) {
#pragma unroll
        for (int l = 0; l < 2; l++) {
            int r = xr + l * 64;
            xs[buf][sw_idx(xkq + 0, r)] = xv[l].x;
            xs[buf][sw_idx(xkq + 1, r)] = xv[l].y;
            xs[buf][sw_idx(xkq + 2, r)] = xv[l].z;
            xs[buf][sw_idx(xkq + 3, r)] = xv[l].w;
            *(uint4*)&ws[buf][sw_idx(wkr + l * 8, wcq)] = wv[l];
        }
    };
    auto compute = [&](int buf) {
#pragma unroll
        for (int ks = 0; ks < 2; ks++) {
            const int klo = ks * 8 + tig;
            const int khi = klo + 4;
            uint32_t a[4][4], b[4][2];
#pragma unroll
            for (int mf = 0; mf < 4; mf++) {
                int m0 = mbase + mf * 16 + g;
                a[mf][0] = xs[buf][sw_idx(klo, m0)];
                a[mf][1] = xs[buf][sw_idx(klo, m0 + 8)];
                a[mf][2] = xs[buf][sw_idx(khi, m0)];
                a[mf][3] = xs[buf][sw_idx(khi, m0 + 8)];
            }
#pragma unroll
            for (int nf = 0; nf < 4; nf++) {
                int n0 = nbase + nf * 8 + g;
                b[nf][0] = ws[buf][sw_idx(klo, n0)];
                b[nf][1] = ws[buf][sw_idx(khi, n0)];
            }
#pragma unroll
            for (int mf = 0; mf < 4; mf++)
#pragma unroll
                for (int nf = 0; nf < 4; nf++)
                    mma_f16(c[mf][nf], a[mf], b[nf]);
        }
    };

    loadg(0);
    store_s(0);
    __syncthreads();

    for (int t = 0; t < NC; t++) {
        if (t + 1 < NC) loadg(t + 1);
        compute(t & 1);
        if (t + 1 < NC) {
            store_s((t + 1) & 1);
            __syncthreads();
        }
    }

#pragma unroll
    for (int mf = 0; mf < 4; mf++) {
        int r0 = row0 + mbase + mf * 16 + g;
#pragma unroll
        for (int nf = 0; nf < 4; nf++) {
            int ncol = nbase + nf * 8 + tig * 2;
            int np = ncol >> 1;
            float b0 = __ldg(&bias[ncol]);
            float b1 = __ldg(&bias[ncol + 1]);
            if (r0 < M)
                Y[(size_t)r0 * 64 + np] =
                    h2_u32(__floats2half2_rn(elu1(b0 + c[mf][nf][0]),
                                             elu1(b1 + c[mf][nf][1])));
            if (r0 + 8 < M)
                Y[(size_t)(r0 + 8) * 64 + np] =
                    h2_u32(__floats2half2_rn(elu1(b0 + c[mf][nf][2]),
                                             elu1(b1 + c[mf][nf][3])));
        }
    }
}

// ---------------- layer-1 aggregation restricted to S (dual) ----------------

__global__ __launch_bounds__(256)
void agg_list(const uint32_t* __restrict__ A0, const uint32_t* __restrict__ A1,
              uint32_t* __restrict__ B0, uint32_t* __restrict__ B1,
              const int* __restrict__ cnt0, const int* __restrict__ cnt1,
              const int* __restrict__ srcs0, const int* __restrict__ srcs1,
              const float* __restrict__ bias0, const float* __restrict__ bias1,
              const int* __restrict__ list0, const int* __restrict__ list1,
              const int* __restrict__ listcnt) {
    const uint32_t* A; uint32_t* B; const int* cnt; const int* srcs;
    const float* bias; const int* list; int lc;
    if (blockIdx.y) { A = A1; B = B1; cnt = cnt1; srcs = srcs1; bias = bias1; list = list1; lc = __ldg(&listcnt[1]); }
    else            { A = A0; B = B0; cnt = cnt0; srcs = srcs0; bias = bias0; list = list0; lc = __ldg(&listcnt[0]); }

    int idx = (blockIdx.x * 256 + threadIdx.x) >> 5;
    if (idx >= lc) return;
    int node = __ldg(&list[idx]);
    int lane = threadIdx.x & 31;

    const uint2* A2 = (const uint2*)A;
    const float dd = dinv_of(__ldg(&cnt[node]));

    float4 a0 = h4_to_f4(A2[(size_t)node * 32 + lane]);
    float4 acc = make_float4(dd * a0.x, dd * a0.y, dd * a0.z, dd * a0.w);

    int c = min(__ldg(&cnt[node]), SLOTS);
    const int* sp = &srcs[(size_t)node * SLOTS];

    int i = 0;
    for (; i + 4 <= c; i += 4) {
        int4 s4 = *(const int4*)&sp[i];
        float n0 = dinv_of(__ldg(&cnt[s4.x]));
        float n1 = dinv_of(__ldg(&cnt[s4.y]));
        float n2 = dinv_of(__ldg(&cnt[s4.z]));
        float n3 = dinv_of(__ldg(&cnt[s4.w]));
        float4 v0 = h4_to_f4(__ldg(&A2[(size_t)s4.x * 32 + lane]));
        float4 v1 = h4_to_f4(__ldg(&A2[(size_t)s4.y * 32 + lane]));
        float4 v2 = h4_to_f4(__ldg(&A2[(size_t)s4.z * 32 + lane]));
        float4 v3 = h4_to_f4(__ldg(&A2[(size_t)s4.w * 32 + lane]));
        acc.x = fmaf(n0, v0.x, acc.x); acc.y = fmaf(n0, v0.y, acc.y);
        acc.z = fmaf(n0, v0.z, acc.z); acc.w = fmaf(n0, v0.w, acc.w);
        acc.x = fmaf(n1, v1.x, acc.x); acc.y = fmaf(n1, v1.y, acc.y);
        acc.z = fmaf(n1, v1.z, acc.z); acc.w = fmaf(n1, v1.w, acc.w);
        acc.x = fmaf(n2, v2.x, acc.x); acc.y = fmaf(n2, v2.y, acc.y);
        acc.z = fmaf(n2, v2.z, acc.z); acc.w = fmaf(n2, v2.w, acc.w);
        acc.x = fmaf(n3, v3.x, acc.x); acc.y = fmaf(n3, v3.y, acc.y);
        acc.z = fmaf(n3, v3.z, acc.z); acc.w = fmaf(n3, v3.w, acc.w);
    }
    for (; i < c; i++) {
        int s = __ldg(&sp[i]);
        float n = dinv_of(__ldg(&cnt[s]));
        float4 v = h4_to_f4(__ldg(&A2[(size_t)s * 32 + lane]));
        acc.x = fmaf(n, v.x, acc.x); acc.y = fmaf(n, v.y, acc.y);
        acc.z = fmaf(n, v.z, acc.z); acc.w = fmaf(n, v.w, acc.w);
    }

    float4 bv = *(const float4*)&bias[lane * 4];
    acc.x = dd * elu1(fmaf(dd, acc.x, bv.x));
    acc.y = dd * elu1(fmaf(dd, acc.y, bv.y));
    acc.z = dd * elu1(fmaf(dd, acc.z, bv.z));
    acc.w = dd * elu1(fmaf(dd, acc.w, bv.w));

    uint2 o;
    o.x = h2_u32(__floats2half2_rn(acc.x, acc.y));
    o.y = h2_u32(__floats2half2_rn(acc.z, acc.w));
    ((uint2*)B)[(size_t)node * 32 + lane] = o;
}

// ---------------- layer-2 gather at roots (dual) ----------------

__global__ __launch_bounds__(256)
void gather2_kernel(const uint32_t* __restrict__ B0, const uint32_t* __restrict__ B1,
                    const int* __restrict__ roots,
                    const int* __restrict__ cnt0, const int* __restrict__ cnt1,
                    const int* __restrict__ srcs0, const int* __restrict__ srcs1,
                    uint32_t* __restrict__ gbuf0, uint32_t* __restrict__ gbuf1, int R) {
    const uint32_t* B; const int* cnt; const int* srcs; uint32_t* gbuf;
    if (blockIdx.y) { B = B1; cnt = cnt1; srcs = srcs1; gbuf = gbuf1; }
    else            { B = B0; cnt = cnt0; srcs = srcs0; gbuf = gbuf0; }

    int r = blockIdx.x * 8 + (threadIdx.x >> 5);
    if (r >= R) return;
    int lane = threadIdx.x & 31;
    int node = __ldg(&roots[r]);

    const uint2* B2 = (const uint2*)B;
    float4 acc = h4_to_f4(B2[(size_t)node * 32 + lane]);

    int c = min(__ldg(&cnt[node]), SLOTS);
    const int* sp = &srcs[(size_t)node * SLOTS];
    for (int i = 0; i < c; i++) {
        int s = __ldg(&sp[i]);
        float4 v = h4_to_f4(__ldg(&B2[(size_t)s * 32 + lane]));
        acc.x += v.x; acc.y += v.y; acc.z += v.z; acc.w += v.w;
    }

    float dd = dinv_of(__ldg(&cnt[node]));
    uint2 o;
    o.x = h2_u32(__floats2half2_rn(dd * acc.x, dd * acc.y));
    o.y = h2_u32(__floats2half2_rn(dd * acc.z, dd * acc.w));
    ((uint2*)gbuf)[(size_t)r * 32 + lane] = o;
}

// ---------------- fused head ----------------

__global__ __launch_bounds__(256)
void head_kernel(const uint32_t* __restrict__ Rtd, const uint32_t* __restrict__ Rbu,
                 const float* __restrict__ fcw, const float* __restrict__ fcb,
                 float* __restrict__ out, int R) {
    int r = blockIdx.x * 8 + (threadIdx.x >> 5);
    if (r >= R) return;
    int lane = threadIdx.x & 31;

    float4 ftd = h4_to_f4(((const uint2*)Rtd)[(size_t)r * 32 + lane]);
    float4 fbu = h4_to_f4(((const uint2*)Rbu)[(size_t)r * 32 + lane]);

    float s0 = 0.f, s1 = 0.f, s2 = 0.f, s3 = 0.f;
    const float* ft = &ftd.x;
    const float* fb = &fbu.x;
#pragma unroll
    for (int j = 0; j < 4; j++) {
        int k = lane * 4 + j;
        float4 wt = *(const float4*)&fcw[(size_t)k * 4];
        float4 wb = *(const float4*)&fcw[(size_t)(128 + k) * 4];
        s0 = fmaf(ft[j], wt.x, fmaf(fb[j], wb.x, s0));
        s1 = fmaf(ft[j], wt.y, fmaf(fb[j], wb.y, s1));
        s2 = fmaf(ft[j], wt.z, fmaf(fb[j], wb.z, s2));
        s3 = fmaf(ft[j], wt.w, fmaf(fb[j], wb.w, s3));
    }
#pragma unroll
    for (int off = 16; off; off >>= 1) {
        s0 += __shfl_xor_sync(0xffffffffu, s0, off);
        s1 += __shfl_xor_sync(0xffffffffu, s1, off);
        s2 += __shfl_xor_sync(0xffffffffu, s2, off);
        s3 += __shfl_xor_sync(0xffffffffu, s3, off);
    }
    if (lane == 0) {
        s0 += fcb[0]; s1 += fcb[1]; s2 += fcb[2]; s3 += fcb[3];
        float m = fmaxf(fmaxf(s0, s1), fmaxf(s2, s3));
        float s = expf(s0 - m) + expf(s1 - m) + expf(s2 - m) + expf(s3 - m);
        float lse = m + logf(s);
        float4 o = make_float4(s0 - lse, s1 - lse, s2 - lse, s3 - lse);
        *(float4*)&out[(size_t)r * 4] = o;
    }
}

// ---------------------------------------------------------------------------

extern "C" void kernel_launch(void* const* d_in, const int* in_sizes, int n_in,
                              void* d_out, int out_size) {
    const float* x       = (const float*)d_in[0];
    const int*   ei_td   = (const int*)d_in[1];
    const int*   ei_bu   = (const int*)d_in[2];
    const int*   rootidx = (const int*)d_in[3];
    const float* w1 = (const float*)d_in[4];
    const float* b1 = (const float*)d_in[5];
    const float* w2 = (const float*)d_in[6];
    const float* b2 = (const float*)d_in[7];
    const float* w3 = (const float*)d_in[8];
    const float* b3 = (const float*)d_in[9];
    const float* w4 = (const float*)d_in[10];
    const float* b4 = (const float*)d_in[11];
    const float* fcw = (const float*)d_in[12];
    const float* fcb = (const float*)d_in[13];
    float* out = (float*)d_out;

    const int N = in_sizes[0] / 256;
    const int E = in_sizes[1] / 2;
    const int R = in_sizes[3];

    const int* src_td = ei_td;
    const int* dst_td = ei_td + E;
    const int* src_bu = ei_bu;
    const int* dst_bu = ei_bu + E;

    uint32_t *A_td, *B_td, *A_bu, *B_bu, *wh, *g_td, *g_bu, *r_td, *r_bu;
    int *cur_td, *cur_bu, *srcs_td, *srcs_bu;
    int *list_td, *list_bu, *listcnt, *mark_td, *mark_bu;
    cudaGetSymbolAddress((void**)&A_td, g_A_td);
    cudaGetSymbolAddress((void**)&B_td, g_B_td);
    cudaGetSymbolAddress((void**)&A_bu, g_A_bu);
    cudaGetSymbolAddress((void**)&B_bu, g_B_bu);
    cudaGetSymbolAddress((void**)&wh, g_wh);
    cudaGetSymbolAddress((void**)&cur_td, g_cur_td);
    cudaGetSymbolAddress((void**)&cur_bu, g_cur_bu);
    cudaGetSymbolAddress((void**)&srcs_td, g_srcs_td);
    cudaGetSymbolAddress((void**)&srcs_bu, g_srcs_bu);
    cudaGetSymbolAddress((void**)&mark_td, g_mark_td);
    cudaGetSymbolAddress((void**)&mark_bu, g_mark_bu);
    cudaGetSymbolAddress((void**)&list_td, g_list_td);
    cudaGetSymbolAddress((void**)&list_bu, g_list_bu);
    cudaGetSymbolAddress((void**)&listcnt, g_listcnt);
    cudaGetSymbolAddress((void**)&g_td, g_g_td);
    cudaGetSymbolAddress((void**)&g_bu, g_g_bu);
    cudaGetSymbolAddress((void**)&r_td, g_r_td);
    cudaGetSymbolAddress((void**)&r_bu, g_r_bu);

    const uint32_t* w2h = wh;
    const uint32_t* w4h = wh + 64 * 128;

    static cudaStream_t sC = nullptr;
    static cudaEvent_t evFork, evPrep;
    if (!sC) {
        cudaStreamCreateWithFlags(&sC, cudaStreamNonBlocking);
        cudaEventCreateWithFlags(&evFork, cudaEventDisableTiming);
        cudaEventCreateWithFlags(&evPrep, cudaEventDisableTiming);
    }
    cudaStream_t sA = 0;

    const int gemm_blocks = ceil_div(N, 128);
    const dim3 agg_grid(ceil_div(N, 8), 2);
    const dim3 gather_grid(ceil_div(R, 8), 2);
    const dim3 root_grid(ceil_div(R, 128), 2);

    cudaEventRecord(evFork, sA);
    cudaStreamWaitEvent(sC, evFork, 0);

    // sC: 3-stage prep chain + weight pack (hidden under the GEMM)
    zero_kernel<<<ceil_div(N, 256), 256, 0, sC>>>(cur_td, cur_bu,
                                                  mark_td, mark_bu, listcnt, N);
    fill_kernel<<<dim3(ceil_div(E, 1024), 2), 256, 0, sC>>>(
        src_td, dst_td, src_bu, dst_bu, cur_td, cur_bu, srcs_td, srcs_bu, E);
    markcompact_kernel<<<dim3(ceil_div(R * 65, 256), 2), 256, 0, sC>>>(
        rootidx, cur_td, srcs_td, cur_bu, srcs_bu, mark_td, mark_bu,
        list_td, list_bu, listcnt, R);
    pack_w_kernel<<<64, 256, 0, sC>>>(w2, w4, wh);
    cudaEventRecord(evPrep, sC);

    // sA: fused dual GEMM (starts at t=0), then dual tails
    gemm_l1_dual<<<gemm_blocks, 256, 0, sA>>>(x, w1, w3, A_td, A_bu, N);
    cudaStreamWaitEvent(sA, evPrep, 0);
    agg_list<<<agg_grid, 256, 0, sA>>>(A_td, A_bu, B_td, B_bu, cur_td, cur_bu,
                                       srcs_td, srcs_bu, b1, b3,
                                       list_td, list_bu, listcnt);
    gather2_kernel<<<gather_grid, 256, 0, sA>>>(B_td, B_bu, rootidx,
                                                cur_td, cur_bu, srcs_td, srcs_bu,
                                                g_td, g_bu, R);
    gemm_root<<<root_grid, 256, 0, sA>>>(g_td, g_bu, w2h, w4h, r_td, r_bu,
                                         b2, b4, R);
    head_kernel<<<ceil_div(R, 8), 256, 0, sA>>>(r_td, r_bu, fcw, fcb, out, R);
}